// round 12
// baseline (speedup 1.0000x reference)
#include <cuda_runtime.h>
#include <cuda_bf16.h>
#include <math.h>
#include <stdint.h>

#define NDOC 4096
#define VW   10000
#define VWP  10048
#define KTOP 100
#define EDIM 384
#define NC1  44      // DT sinkhorn CTAs
#define NC2  104     // TW sinkhorn CTAs

// ---------------- device state -----------------------------------------------
__device__ __align__(16) float g_Mdt[NDOC*KTOP];
__device__ __align__(16) float g_Kdt[NDOC*KTOP];
__device__ __align__(16) float g_MtwT[VW*KTOP];
__device__ __align__(16) float g_KtwT[VW*KTOP];
__device__ __align__(16) __nv_bfloat16 g_thetaB[NDOC*128];
__device__ __align__(16) __nv_bfloat16 g_betaB[VWP*128];
__device__ __align__(16) float g_u1[NDOC];
__device__ __align__(16) float g_v1fin[128];
__device__ __align__(16) float g_b1[128];
__device__ __align__(16) float g_u2[128];
__device__ __align__(16) float g_v2[VW];
__device__ __align__(16) float g_v2fin[VW];
__device__ __align__(16) float g_b2[VW];
__device__ float g_nd[NDOC], g_nt[KTOP], g_nw[VW];
__device__ float g_s1[3][128];     // triple-buffered K^T u accumulators (DT)
__device__ float g_s2[3][128];     // triple-buffered K v accumulators (TW)
__device__ float g_err2[NC2];
__device__ double g_acc[3];
__device__ unsigned g_bc1, g_bc2, g_bc3;
__device__ volatile unsigned g_bg1, g_bg2, g_bg3;

// ---------------- helpers ----------------------------------------------------
__device__ __forceinline__ float warp_bfly(float v){
    v += __shfl_xor_sync(0xffffffffu, v, 16);
    v += __shfl_xor_sync(0xffffffffu, v, 8);
    v += __shfl_xor_sync(0xffffffffu, v, 4);
    v += __shfl_xor_sync(0xffffffffu, v, 2);
    v += __shfl_xor_sync(0xffffffffu, v, 1);
    return v;
}
__device__ __forceinline__ float warp_sum(float v){
    v += __shfl_down_sync(0xffffffffu, v, 16);
    v += __shfl_down_sync(0xffffffffu, v, 8);
    v += __shfl_down_sync(0xffffffffu, v, 4);
    v += __shfl_down_sync(0xffffffffu, v, 2);
    v += __shfl_down_sync(0xffffffffu, v, 1);
    return v;
}
__device__ __forceinline__ void gbar(unsigned* cnt, volatile unsigned* gen, unsigned nb){
    __syncthreads();
    if (threadIdx.x == 0){
        __threadfence();
        unsigned g = *gen;
        if (atomicAdd(cnt, 1u) == nb - 1u){
            *cnt = 0u; __threadfence(); *gen = g + 1u;
        } else {
            while (*gen == g) { __nanosleep(32); }
            __threadfence();
        }
    }
    __syncthreads();
}

// ---------------- fused prologue: init + norms + softmax ----------------------
__global__ __launch_bounds__(256) void prologue_kernel(
    const float* __restrict__ doc, const float* __restrict__ topic,
    const float* __restrict__ word, const float* __restrict__ tw,
    const float* __restrict__ ww)
{
    __shared__ float red[256];
    int b = blockIdx.x, tid = threadIdx.x;
    if (b < 148){
        int lane = tid & 31, w = tid >> 5;
        int gw = b*8 + w;
        const int TOT = NDOC + KTOP + VW;
        for (int row = gw; row < TOT; row += 148*8){
            const float4* src; float* dst;
            if (row < NDOC){ src = (const float4*)(doc + (size_t)row*EDIM); dst = &g_nd[row]; }
            else if (row < NDOC + KTOP){ src = (const float4*)(topic + (size_t)(row-NDOC)*EDIM); dst = &g_nt[row-NDOC]; }
            else { src = (const float4*)(word + (size_t)(row-NDOC-KTOP)*EDIM); dst = &g_nw[row-NDOC-KTOP]; }
            float4 a = src[lane], c = src[lane+32], d = src[lane+64];
            float s = a.x*a.x + a.y*a.y + a.z*a.z + a.w*a.w
                    + c.x*c.x + c.y*c.y + c.z*c.z + c.w*c.w
                    + d.x*d.x + d.y*d.y + d.z*d.z + d.w*d.w;
            s = warp_sum(s);
            if (lane == 0) *dst = s;
        }
    } else if (b == 148 || b == 149){
        const float* x = (b == 148) ? tw : ww;
        float* out = (b == 148) ? g_b1 : g_b2;
        int n = (b == 148) ? KTOP : VW;
        float m = -3.4e38f;
        for (int i = tid; i < n; i += 256) m = fmaxf(m, x[i]);
        red[tid] = m; __syncthreads();
        for (int s = 128; s > 0; s >>= 1){ if (tid < s) red[tid] = fmaxf(red[tid], red[tid+s]); __syncthreads(); }
        m = red[0]; __syncthreads();
        float sum = 0.f;
        for (int i = tid; i < n; i += 256) sum += expf(x[i] - m);
        red[tid] = sum; __syncthreads();
        for (int s = 128; s > 0; s >>= 1){ if (tid < s) red[tid] += red[tid+s]; __syncthreads(); }
        sum = red[0]; __syncthreads();
        float inv = 1.0f / sum;
        for (int i = tid; i < n; i += 256) out[i] = expf(x[i] - m) * inv;
    } else {
        if (tid == 0){
            g_bc1 = 0u; g_bc2 = 0u; g_bc3 = 0u;
            g_bg1 = 0u; g_bg2 = 0u; g_bg3 = 0u;
            g_acc[0] = 0.0; g_acc[1] = 0.0; g_acc[2] = 0.0;
        }
        if (tid < 128){
#pragma unroll
            for (int q = 0; q < 3; q++){ g_s1[q][tid] = 0.f; g_s2[q][tid] = 0.f; }
        }
    }
}

// ---------------- tf32 tensor-core distance kernel ----------------------------
__global__ __launch_bounds__(256) void dist_mma(
    const float* __restrict__ doc, const float* __restrict__ word,
    const float* __restrict__ topic)
{
    __shared__ float As[128*36];
    __shared__ float Bs[128*36];
    int tid = threadIdx.x, lane = tid & 31, w = tid >> 5;
    int wr = w >> 1, wc = w & 1;
    int g = lane >> 2, c = lane & 3;
    int by = blockIdx.x;
    bool dt = (by < 32);
    const float* A = dt ? doc : word;
    int nA = dt ? NDOC : VW;
    int r0 = (dt ? by : (by - 32)) * 128;
    float alpha = dt ? 3.0f : 2.0f;
    const float* nAarr = dt ? g_nd : g_nw;
    float* Mo = dt ? g_Mdt : g_MtwT;
    float* Ko = dt ? g_Kdt : g_KtwT;

    float acc[2][8][4];
#pragma unroll
    for (int mi = 0; mi < 2; mi++)
#pragma unroll
        for (int ni = 0; ni < 8; ni++)
#pragma unroll
            for (int q = 0; q < 4; q++) acc[mi][ni][q] = 0.f;

    for (int chunk = 0; chunk < 12; chunk++){
        int kc = chunk * 32;
        __syncthreads();
        for (int f = tid; f < 1024; f += 256){
            int r = f >> 3, q = f & 7;
            float4 v = make_float4(0,0,0,0);
            if (r0 + r < nA) v = *(const float4*)&A[(size_t)(r0 + r)*EDIM + kc + q*4];
            *(float4*)&As[r*36 + q*4] = v;
        }
        for (int f = tid; f < 1024; f += 256){
            int r = f >> 3, q = f & 7;
            float4 v = make_float4(0,0,0,0);
            if (r < KTOP) v = *(const float4*)&topic[(size_t)r*EDIM + kc + q*4];
            *(float4*)&Bs[r*36 + q*4] = v;
        }
        __syncthreads();
#pragma unroll
        for (int ks = 0; ks < 4; ks++){
            int ka = ks*8 + c;
            uint32_t a0[2], a1[2], a2[2], a3[2], b0[8], b1[8];
#pragma unroll
            for (int mi = 0; mi < 2; mi++){
                int base = (wr*32 + mi*16 + g)*36 + ka;
                a0[mi] = __float_as_uint(As[base]);
                a1[mi] = __float_as_uint(As[base + 8*36]);
                a2[mi] = __float_as_uint(As[base + 4]);
                a3[mi] = __float_as_uint(As[base + 8*36 + 4]);
            }
#pragma unroll
            for (int ni = 0; ni < 8; ni++){
                int nb = (wc*64 + ni*8 + g)*36 + ka;
                b0[ni] = __float_as_uint(Bs[nb]);
                b1[ni] = __float_as_uint(Bs[nb + 4]);
            }
#pragma unroll
            for (int mi = 0; mi < 2; mi++)
#pragma unroll
                for (int ni = 0; ni < 8; ni++){
                    asm volatile(
                        "mma.sync.aligned.m16n8k8.row.col.f32.tf32.tf32.f32 "
                        "{%0,%1,%2,%3}, {%4,%5,%6,%7}, {%8,%9}, {%0,%1,%2,%3};"
                        : "+f"(acc[mi][ni][0]), "+f"(acc[mi][ni][1]),
                          "+f"(acc[mi][ni][2]), "+f"(acc[mi][ni][3])
                        : "r"(a0[mi]), "r"(a1[mi]), "r"(a2[mi]), "r"(a3[mi]),
                          "r"(b0[ni]), "r"(b1[ni]));
                }
        }
    }

#pragma unroll
    for (int mi = 0; mi < 2; mi++){
        int Rb = r0 + wr*32 + mi*16 + g;
#pragma unroll
        for (int ni = 0; ni < 8; ni++){
            int Cb = wc*64 + ni*8 + c*2;
#pragma unroll
            for (int q = 0; q < 4; q++){
                int R = Rb + ((q >= 2) ? 8 : 0);
                int C = Cb + (q & 1);
                if (R < nA && C < KTOP){
                    float M = nAarr[R] + g_nt[C] - 2.0f * acc[mi][ni][q];
                    float kv = expf(-alpha * M);
                    Mo[(size_t)R*KTOP + C] = M;
                    Ko[(size_t)R*KTOP + C] = kv;
                }
            }
        }
    }
}

// ---------------- fused persistent Sinkhorn + tb epilogue ---------------------
__device__ void sink_dt(int cta){
    __shared__ float v_sm[128], vf_sm[128], b_sm[128], spw[8][128], red[256];
    int tid = threadIdx.x, w = tid >> 5, lane = tid & 31;
    int gwid = cta*8 + w;
    const int NWRP = NC1*8;
    const float invN = 1.0f / (float)NDOC;

    if (tid < 128) b_sm[tid] = (tid < 100) ? g_b1[tid] : 0.f;
    // prologue: s0 = K^T u0 with u0 = 1/N, accumulate into buf 0
    {
        float4 p = make_float4(0,0,0,0);
        for (int i = gwid; i < NDOC; i += NWRP){
            if (lane < 25){
                float4 k = ((const float4*)(g_Kdt + (size_t)i*KTOP))[lane];
                p.x += k.x; p.y += k.y; p.z += k.z; p.w += k.w;
            }
        }
        if (lane < 25){
            spw[w][4*lane]   = p.x*invN; spw[w][4*lane+1] = p.y*invN;
            spw[w][4*lane+2] = p.z*invN; spw[w][4*lane+3] = p.w*invN;
        }
    }
    __syncthreads();
    if (tid < 100){
        float s = 0.f;
#pragma unroll
        for (int x = 0; x < 8; x++) s += spw[x][tid];
        atomicAdd(&g_s1[0][tid], s);
    }
    gbar(&g_bc1, &g_bg1, NC1);
    if (tid < 128) v_sm[tid] = (tid < 100) ? (b_sm[tid] / (g_s1[0][tid] + 1e-16f)) : 0.f;
    __syncthreads();

    float err = 1.0f; int cpt = 0;
    while (err > 0.005f && cpt < 5000){
        int it = cpt + 1;
        int buf = it % 3;
        bool chk = ((it % 50) == 1) || (it == 5000);   // err check + possible exit
        if (cta == 0 && tid < 128) g_s1[(it + 1) % 3][tid] = 0.f;  // safe: last read pre-gbar(it-1)
        float4 vv = (lane < 25) ? ((const float4*)v_sm)[lane] : make_float4(0,0,0,0);
        float4 p = make_float4(0,0,0,0);
        for (int i = gwid; i < NDOC; i += 2*NWRP){
            int i2 = i + NWRP;
            float4 ka = make_float4(0,0,0,0), kb = make_float4(0,0,0,0);
            if (lane < 25){
                ka = ((const float4*)(g_Kdt + (size_t)i*KTOP))[lane];
                if (i2 < NDOC) kb = ((const float4*)(g_Kdt + (size_t)i2*KTOP))[lane];
            }
            float ta = ka.x*vv.x + ka.y*vv.y + ka.z*vv.z + ka.w*vv.w;
            float tb = kb.x*vv.x + kb.y*vv.y + kb.z*vv.z + kb.w*vv.w;
            ta = warp_bfly(ta); tb = warp_bfly(tb);
            float ua = invN / (ta + 1e-16f);
            if (lane == 0 && chk) g_u1[i] = ua;   // u only needed at exit-capable iters
            p.x += ka.x*ua; p.y += ka.y*ua; p.z += ka.z*ua; p.w += ka.w*ua;
            if (i2 < NDOC){
                float ub = invN / (tb + 1e-16f);
                if (lane == 0 && chk) g_u1[i2] = ub;
                p.x += kb.x*ub; p.y += kb.y*ub; p.z += kb.z*ub; p.w += kb.w*ub;
            }
        }
        if (lane < 25){
            spw[w][4*lane] = p.x; spw[w][4*lane+1] = p.y;
            spw[w][4*lane+2] = p.z; spw[w][4*lane+3] = p.w;
        }
        __syncthreads();
        if (tid < 100){
            float s = 0.f;
#pragma unroll
            for (int x = 0; x < 8; x++) s += spw[x][tid];
            atomicAdd(&g_s1[buf][tid], s);
        }
        cpt = it;
        gbar(&g_bc1, &g_bg1, NC1);
        float ev = 0.f;
        if (tid < 128){
            float s = (tid < 100) ? g_s1[buf][tid] : 0.f;
            float vo = v_sm[tid];
            vf_sm[tid] = vo;
            if (chk && tid < 100) ev = fabsf(vo*s - b_sm[tid]);
            v_sm[tid] = (tid < 100) ? (b_sm[tid] / (s + 1e-16f)) : 0.f;
        }
        if (chk){
            red[tid] = ev; __syncthreads();
            for (int s2 = 128; s2 > 0; s2 >>= 1){ if (tid < s2) red[tid] += red[tid+s2]; __syncthreads(); }
            err = red[0];
        }
        __syncthreads();
    }
    if (cta == 0 && tid < 100) g_v1fin[tid] = vf_sm[tid];
}

__device__ void sink_tw(int cta){
    __shared__ float u_sm[128], spw[8][128], red[256];
    int tid = threadIdx.x, w = tid >> 5, lane = tid & 31;
    int gwid = cta*8 + w;
    const int NWRP = NC2*8;
    const float invK = 1.0f / (float)KTOP;

    // prologue: v1 = b/(K^T u0); accumulate r1 = K v1 into buf 0
    {
        float4 p = make_float4(0,0,0,0);
        for (int j = gwid; j < VW; j += NWRP){
            float4 k = make_float4(0,0,0,0);
            if (lane < 25) k = ((const float4*)(g_KtwT + (size_t)j*KTOP))[lane];
            float t = warp_bfly(k.x + k.y + k.z + k.w) * invK;
            float v = g_b2[j] / (t + 1e-16f);
            if (lane == 0) g_v2[j] = v;       // v_1, read by chk at it=1
            p.x += k.x*v; p.y += k.y*v; p.z += k.z*v; p.w += k.w*v;
        }
        if (lane < 25){
            spw[w][4*lane] = p.x; spw[w][4*lane+1] = p.y;
            spw[w][4*lane+2] = p.z; spw[w][4*lane+3] = p.w;
        }
    }
    __syncthreads();
    if (tid < 100){
        float s = 0.f;
#pragma unroll
        for (int x = 0; x < 8; x++) s += spw[x][tid];
        atomicAdd(&g_s2[0][tid], s);
    }
    gbar(&g_bc2, &g_bg2, NC2);

    float err = 1.0f; int cpt = 0;
    while (err > 0.005f && cpt < 5000){
        int it = cpt + 1;
        int buf = it % 3;
        bool chk = ((it % 50) == 1) || (it == 5000);
        bool stv = ((it % 50) == 0) || (it == 4999);     // next iter reads old v
        if (cta == 0 && tid < 128) g_s2[(it + 1) % 3][tid] = 0.f;
        if (tid < 128) u_sm[tid] = (tid < 100) ? (invK / (g_s2[(it + 2) % 3][tid] + 1e-16f)) : 0.f;
        __syncthreads();
        float4 uu = (lane < 25) ? ((const float4*)u_sm)[lane] : make_float4(0,0,0,0);
        float4 p = make_float4(0,0,0,0);
        float ep = 0.f;
        for (int j = gwid; j < VW; j += 2*NWRP){
            int j2 = j + NWRP;
            float4 ka = make_float4(0,0,0,0), kb = make_float4(0,0,0,0);
            if (lane < 25){
                ka = ((const float4*)(g_KtwT + (size_t)j*KTOP))[lane];
                if (j2 < VW) kb = ((const float4*)(g_KtwT + (size_t)j2*KTOP))[lane];
            }
            float ta = ka.x*uu.x + ka.y*uu.y + ka.z*uu.z + ka.w*uu.w;
            float tb = kb.x*uu.x + kb.y*uu.y + kb.z*uu.z + kb.w*uu.w;
            ta = warp_bfly(ta); tb = warp_bfly(tb);
            float bja = g_b2[j];
            float vna = bja / (ta + 1e-16f);
            if (lane == 0){
                if (chk){ float vo = g_v2[j]; ep += fabsf(vo*ta - bja); g_v2fin[j] = vo; }
                if (stv) g_v2[j] = vna;
            }
            p.x += ka.x*vna; p.y += ka.y*vna; p.z += ka.z*vna; p.w += ka.w*vna;
            if (j2 < VW){
                float bjb = g_b2[j2];
                float vnb = bjb / (tb + 1e-16f);
                if (lane == 0){
                    if (chk){ float vo = g_v2[j2]; ep += fabsf(vo*tb - bjb); g_v2fin[j2] = vo; }
                    if (stv) g_v2[j2] = vnb;
                }
                p.x += kb.x*vnb; p.y += kb.y*vnb; p.z += kb.z*vnb; p.w += kb.w*vnb;
            }
        }
        if (lane < 25){
            spw[w][4*lane] = p.x; spw[w][4*lane+1] = p.y;
            spw[w][4*lane+2] = p.z; spw[w][4*lane+3] = p.w;
        }
        if (chk){
            red[tid] = ep; __syncthreads();
            for (int s2 = 128; s2 > 0; s2 >>= 1){ if (tid < s2) red[tid] += red[tid+s2]; __syncthreads(); }
            if (tid == 0) g_err2[cta] = red[0];
        }
        __syncthreads();
        if (tid < 100){
            float s = 0.f;
#pragma unroll
            for (int x = 0; x < 8; x++) s += spw[x][tid];
            atomicAdd(&g_s2[buf][tid], s);
        }
        cpt = it;
        gbar(&g_bc2, &g_bg2, NC2);
        if (chk){
            red[tid] = (tid < NC2) ? g_err2[tid] : 0.f; __syncthreads();
            for (int s2 = 128; s2 > 0; s2 >>= 1){ if (tid < s2) red[tid] += red[tid+s2]; __syncthreads(); }
            err = red[0];
        }
        __syncthreads();
    }
    if (cta == 0 && tid < 100) g_u2[tid] = u_sm[tid];
}

// theta/beta production + transport losses, vectorized, on the 148 resident CTAs
__device__ void tb_phase(int cta){
    __shared__ float red[256];
    int tid = threadIdx.x;
    const int TH = NDOC*32;
    const int TOT = TH + VWP*32;
    float pth = 0.f, pbe = 0.f;
    for (int idx = cta*256 + tid; idx < TOT; idx += 148*256){
        if (idx < TH){
            int i = idx >> 5, k4 = (idx & 31) << 2;
            float4 o = make_float4(0,0,0,0);
            if (k4 < KTOP){
                float4 kk = *(const float4*)&g_Kdt[(size_t)i*KTOP + k4];
                float4 mm = *(const float4*)&g_Mdt[(size_t)i*KTOP + k4];
                float4 vf = *(const float4*)&g_v1fin[k4];
                float u = g_u1[i];
                float t0 = u*kk.x*vf.x, t1 = u*kk.y*vf.y, t2 = u*kk.z*vf.z, t3 = u*kk.w*vf.w;
                pth += t0*mm.x + t1*mm.y + t2*mm.z + t3*mm.w;
                o = make_float4(t0*(float)NDOC, t1*(float)NDOC, t2*(float)NDOC, t3*(float)NDOC);
            }
            __nv_bfloat162 lo = __floats2bfloat162_rn(o.x, o.y);
            __nv_bfloat162 hi = __floats2bfloat162_rn(o.z, o.w);
            uint2 st; st.x = *(uint32_t*)&lo; st.y = *(uint32_t*)&hi;
            *(uint2*)&g_thetaB[(size_t)i*128 + k4] = st;
        } else {
            int jdx = idx - TH;
            int j = jdx >> 5, k4 = (jdx & 31) << 2;
            float4 o = make_float4(0,0,0,0);
            if (j < VW && k4 < KTOP){
                float4 kk = *(const float4*)&g_KtwT[(size_t)j*KTOP + k4];
                float4 mm = *(const float4*)&g_MtwT[(size_t)j*KTOP + k4];
                float4 uu = *(const float4*)&g_u2[k4];
                float v = g_v2fin[j];
                float t0 = uu.x*kk.x*v, t1 = uu.y*kk.y*v, t2 = uu.z*kk.z*v, t3 = uu.w*kk.w*v;
                pbe += t0*mm.x + t1*mm.y + t2*mm.z + t3*mm.w;
                o = make_float4(t0*(float)KTOP, t1*(float)KTOP, t2*(float)KTOP, t3*(float)KTOP);
            }
            __nv_bfloat162 lo = __floats2bfloat162_rn(o.x, o.y);
            __nv_bfloat162 hi = __floats2bfloat162_rn(o.z, o.w);
            uint2 st; st.x = *(uint32_t*)&lo; st.y = *(uint32_t*)&hi;
            *(uint2*)&g_betaB[(size_t)j*128 + k4] = st;
        }
    }
    red[tid] = pth; __syncthreads();
    for (int s = 128; s > 0; s >>= 1){ if (tid < s) red[tid] += red[tid+s]; __syncthreads(); }
    if (tid == 0) atomicAdd(&g_acc[0], (double)red[0]);
    __syncthreads();
    red[tid] = pbe; __syncthreads();
    for (int s = 128; s > 0; s >>= 1){ if (tid < s) red[tid] += red[tid+s]; __syncthreads(); }
    if (tid == 0) atomicAdd(&g_acc[1], (double)red[0]);
}

__global__ __launch_bounds__(256) void sink_fused(){
    if (blockIdx.x < NC1) sink_dt(blockIdx.x);
    else                  sink_tw(blockIdx.x - NC1);
    gbar(&g_bc3, &g_bg3, NC1 + NC2);
    tb_phase(blockIdx.x);
}

// ---------------- tensor-core recon GEMM + log-loss --------------------------
__global__ __launch_bounds__(256, 2) void recon_kernel(const float* __restrict__ bow){
    __shared__ __nv_bfloat16 As[128*72];
    __shared__ __nv_bfloat16 Bs[64*72];
    __shared__ float red[256];
    int tid = threadIdx.x, lane = tid & 31, w = tid >> 5;
    int wr = w >> 1, wc = w & 1;
    int g = lane >> 2, c = lane & 3;
    int r0 = blockIdx.y * 128, c0 = blockIdx.x * 64;

    float2 bwreg[2][4][2];
#pragma unroll
    for (int mi = 0; mi < 2; mi++){
        int R = r0 + wr*32 + mi*16 + g;
#pragma unroll
        for (int ni = 0; ni < 4; ni++){
            int C = c0 + wc*32 + ni*8 + c*2;
            if (C < VW){
                bwreg[mi][ni][0] = *(const float2*)&bow[(size_t)R*VW + C];
                bwreg[mi][ni][1] = *(const float2*)&bow[(size_t)(R + 8)*VW + C];
            } else {
                bwreg[mi][ni][0] = make_float2(0.f, 0.f);
                bwreg[mi][ni][1] = make_float2(0.f, 0.f);
            }
        }
    }

    float acc[2][4][4];
#pragma unroll
    for (int mi = 0; mi < 2; mi++)
#pragma unroll
        for (int ni = 0; ni < 4; ni++)
#pragma unroll
            for (int q = 0; q < 4; q++) acc[mi][ni][q] = 0.f;

    const uint32_t* Aw = (const uint32_t*)As;
    const uint32_t* Bw = (const uint32_t*)Bs;
    int rabase = (wr*32 + g)*36;
    int rbbase = (wc*32 + g)*36;

    for (int chunk = 0; chunk < 2; chunk++){
        __syncthreads();
        for (int f = tid; f < 1024; f += 256){
            int r = f >> 3, q = f & 7;
            uint4 val = *(const uint4*)&g_thetaB[(size_t)(r0 + r)*128 + chunk*64 + q*8];
            *(uint4*)&As[r*72 + q*8] = val;
        }
        for (int f = tid; f < 512; f += 256){
            int r = f >> 3, q = f & 7;
            uint4 val = *(const uint4*)&g_betaB[(size_t)(c0 + r)*128 + chunk*64 + q*8];
            *(uint4*)&Bs[r*72 + q*8] = val;
        }
        __syncthreads();
#pragma unroll
        for (int ks = 0; ks < 4; ks++){
            int ka = ks*8 + c;
            uint32_t a0[2], a1[2], a2[2], a3[2], b0[4], b1[4];
#pragma unroll
            for (int mi = 0; mi < 2; mi++){
                int base = rabase + mi*16*36 + ka;
                a0[mi] = Aw[base]; a1[mi] = Aw[base + 8*36];
                a2[mi] = Aw[base + 4]; a3[mi] = Aw[base + 8*36 + 4];
            }
#pragma unroll
            for (int ni = 0; ni < 4; ni++){
                int base = rbbase + ni*8*36 + ka;
                b0[ni] = Bw[base]; b1[ni] = Bw[base + 4];
            }
#pragma unroll
            for (int mi = 0; mi < 2; mi++)
#pragma unroll
                for (int ni = 0; ni < 4; ni++){
                    asm volatile(
                        "mma.sync.aligned.m16n8k16.row.col.f32.bf16.bf16.f32 "
                        "{%0,%1,%2,%3}, {%4,%5,%6,%7}, {%8,%9}, {%0,%1,%2,%3};"
                        : "+f"(acc[mi][ni][0]), "+f"(acc[mi][ni][1]),
                          "+f"(acc[mi][ni][2]), "+f"(acc[mi][ni][3])
                        : "r"(a0[mi]), "r"(a1[mi]), "r"(a2[mi]), "r"(a3[mi]),
                          "r"(b0[ni]), "r"(b1[ni]));
                }
        }
    }

    float part = 0.f;
#pragma unroll
    for (int mi = 0; mi < 2; mi++)
#pragma unroll
        for (int ni = 0; ni < 4; ni++){
            part += bwreg[mi][ni][0].x * __logf(acc[mi][ni][0] + 1e-12f)
                  + bwreg[mi][ni][0].y * __logf(acc[mi][ni][1] + 1e-12f)
                  + bwreg[mi][ni][1].x * __logf(acc[mi][ni][2] + 1e-12f)
                  + bwreg[mi][ni][1].y * __logf(acc[mi][ni][3] + 1e-12f);
        }
    red[tid] = part; __syncthreads();
    for (int s = 128; s > 0; s >>= 1){ if (tid < s) red[tid] += red[tid+s]; __syncthreads(); }
    if (tid == 0) atomicAdd(&g_acc[2], (double)red[0]);
}

__global__ void final_kernel(float* out){
    out[0] = (float)(g_acc[0] + g_acc[1] - g_acc[2] * (1.0 / (double)NDOC));
}

// ---------------- launch -----------------------------------------------------
extern "C" void kernel_launch(void* const* d_in, const int* in_sizes, int n_in,
                              void* d_out, int out_size)
{
    const float *bow = nullptr, *doc = nullptr, *word = nullptr,
                *topic = nullptr, *ww = nullptr, *tw = nullptr;
    for (int i = 0; i < n_in; i++){
        const float* p = (const float*)d_in[i];
        switch (in_sizes[i]){
            case 40960000: bow = p;   break;
            case 1572864:  doc = p;   break;
            case 3840000:  word = p;  break;
            case 38400:    topic = p; break;
            case 10000:    ww = p;    break;
            case 100:      tw = p;    break;
        }
    }
    float* out = (float*)d_out;

    prologue_kernel<<<151, 256>>>(doc, topic, word, tw, ww);
    dist_mma<<<32 + 79, 256>>>(doc, word, topic);
    sink_fused<<<NC1 + NC2, 256>>>();
    recon_kernel<<<dim3(157, 32), 256>>>(bow);
    final_kernel<<<1, 1>>>(out);
}

// round 13
// speedup vs baseline: 1.0083x; 1.0083x over previous
#include <cuda_runtime.h>
#include <cuda_bf16.h>
#include <math.h>
#include <stdint.h>

#define NDOC 4096
#define VW   10000
#define VWP  10112           // 79*128
#define KTOP 100
#define EDIM 384
#define NC1  44      // DT sinkhorn CTAs
#define NC2  104     // TW sinkhorn CTAs

// ---------------- device state -----------------------------------------------
__device__ __align__(16) float g_Mdt[NDOC*KTOP];
__device__ __align__(16) float g_Kdt[NDOC*KTOP];
__device__ __align__(16) float g_MtwT[VW*KTOP];
__device__ __align__(16) float g_KtwT[VW*KTOP];
__device__ __align__(16) __nv_bfloat16 g_thetaB[NDOC*128];
__device__ __align__(16) __nv_bfloat16 g_betaB[VWP*128];
__device__ __align__(16) float g_u1[NDOC];
__device__ __align__(16) float g_v1fin[128];
__device__ __align__(16) float g_b1[128];
__device__ __align__(16) float g_u2[128];
__device__ __align__(16) float g_v2[VW];
__device__ __align__(16) float g_v2fin[VW];
__device__ __align__(16) float g_b2[VW];
__device__ float g_nd[NDOC], g_nt[KTOP], g_nw[VW];
__device__ float g_s1[3][128];     // triple-buffered K^T u accumulators (DT)
__device__ float g_s2[3][128];     // triple-buffered K v accumulators (TW)
__device__ float g_err2[NC2];
__device__ double g_acc[3];
__device__ unsigned g_bc1, g_bc2, g_bc3;
__device__ volatile unsigned g_bg1, g_bg2, g_bg3;

// ---------------- helpers ----------------------------------------------------
__device__ __forceinline__ float warp_bfly(float v){
    v += __shfl_xor_sync(0xffffffffu, v, 16);
    v += __shfl_xor_sync(0xffffffffu, v, 8);
    v += __shfl_xor_sync(0xffffffffu, v, 4);
    v += __shfl_xor_sync(0xffffffffu, v, 2);
    v += __shfl_xor_sync(0xffffffffu, v, 1);
    return v;
}
__device__ __forceinline__ float warp_sum(float v){
    v += __shfl_down_sync(0xffffffffu, v, 16);
    v += __shfl_down_sync(0xffffffffu, v, 8);
    v += __shfl_down_sync(0xffffffffu, v, 4);
    v += __shfl_down_sync(0xffffffffu, v, 2);
    v += __shfl_down_sync(0xffffffffu, v, 1);
    return v;
}
__device__ __forceinline__ void gbar(unsigned* cnt, volatile unsigned* gen, unsigned nb){
    __syncthreads();
    if (threadIdx.x == 0){
        __threadfence();
        unsigned g = *gen;
        if (atomicAdd(cnt, 1u) == nb - 1u){
            *cnt = 0u; __threadfence(); *gen = g + 1u;
        } else {
            while (*gen == g) { __nanosleep(32); }
            __threadfence();
        }
    }
    __syncthreads();
}
__device__ __forceinline__ uint32_t smem_u32(const void* p){
    uint32_t a;
    asm("{ .reg .u64 t; cvta.to.shared.u64 t, %1; cvt.u32.u64 %0, t; }" : "=r"(a) : "l"(p));
    return a;
}

// ---------------- fused prologue: init + norms + softmax ----------------------
__global__ __launch_bounds__(256) void prologue_kernel(
    const float* __restrict__ doc, const float* __restrict__ topic,
    const float* __restrict__ word, const float* __restrict__ tw,
    const float* __restrict__ ww)
{
    __shared__ float red[256];
    int b = blockIdx.x, tid = threadIdx.x;
    if (b < 148){
        int lane = tid & 31, w = tid >> 5;
        int gw = b*8 + w;
        const int TOT = NDOC + KTOP + VW;
        for (int row = gw; row < TOT; row += 148*8){
            const float4* src; float* dst;
            if (row < NDOC){ src = (const float4*)(doc + (size_t)row*EDIM); dst = &g_nd[row]; }
            else if (row < NDOC + KTOP){ src = (const float4*)(topic + (size_t)(row-NDOC)*EDIM); dst = &g_nt[row-NDOC]; }
            else { src = (const float4*)(word + (size_t)(row-NDOC-KTOP)*EDIM); dst = &g_nw[row-NDOC-KTOP]; }
            float4 a = src[lane], c = src[lane+32], d = src[lane+64];
            float s = a.x*a.x + a.y*a.y + a.z*a.z + a.w*a.w
                    + c.x*c.x + c.y*c.y + c.z*c.z + c.w*c.w
                    + d.x*d.x + d.y*d.y + d.z*d.z + d.w*d.w;
            s = warp_sum(s);
            if (lane == 0) *dst = s;
        }
    } else if (b == 148 || b == 149){
        const float* x = (b == 148) ? tw : ww;
        float* out = (b == 148) ? g_b1 : g_b2;
        int n = (b == 148) ? KTOP : VW;
        float m = -3.4e38f;
        for (int i = tid; i < n; i += 256) m = fmaxf(m, x[i]);
        red[tid] = m; __syncthreads();
        for (int s = 128; s > 0; s >>= 1){ if (tid < s) red[tid] = fmaxf(red[tid], red[tid+s]); __syncthreads(); }
        m = red[0]; __syncthreads();
        float sum = 0.f;
        for (int i = tid; i < n; i += 256) sum += expf(x[i] - m);
        red[tid] = sum; __syncthreads();
        for (int s = 128; s > 0; s >>= 1){ if (tid < s) red[tid] += red[tid+s]; __syncthreads(); }
        sum = red[0]; __syncthreads();
        float inv = 1.0f / sum;
        for (int i = tid; i < n; i += 256) out[i] = expf(x[i] - m) * inv;
    } else {
        if (tid == 0){
            g_bc1 = 0u; g_bc2 = 0u; g_bc3 = 0u;
            g_bg1 = 0u; g_bg2 = 0u; g_bg3 = 0u;
            g_acc[0] = 0.0; g_acc[1] = 0.0; g_acc[2] = 0.0;
        }
        if (tid < 128){
#pragma unroll
            for (int q = 0; q < 3; q++){ g_s1[q][tid] = 0.f; g_s2[q][tid] = 0.f; }
        }
    }
}

// ---------------- tf32 tensor-core distance kernel ----------------------------
__global__ __launch_bounds__(256) void dist_mma(
    const float* __restrict__ doc, const float* __restrict__ word,
    const float* __restrict__ topic)
{
    __shared__ float As[128*36];
    __shared__ float Bs[128*36];
    int tid = threadIdx.x, lane = tid & 31, w = tid >> 5;
    int wr = w >> 1, wc = w & 1;
    int g = lane >> 2, c = lane & 3;
    int by = blockIdx.x;
    bool dt = (by < 32);
    const float* A = dt ? doc : word;
    int nA = dt ? NDOC : VW;
    int r0 = (dt ? by : (by - 32)) * 128;
    float alpha = dt ? 3.0f : 2.0f;
    const float* nAarr = dt ? g_nd : g_nw;
    float* Mo = dt ? g_Mdt : g_MtwT;
    float* Ko = dt ? g_Kdt : g_KtwT;

    float acc[2][8][4];
#pragma unroll
    for (int mi = 0; mi < 2; mi++)
#pragma unroll
        for (int ni = 0; ni < 8; ni++)
#pragma unroll
            for (int q = 0; q < 4; q++) acc[mi][ni][q] = 0.f;

    for (int chunk = 0; chunk < 12; chunk++){
        int kc = chunk * 32;
        __syncthreads();
        for (int f = tid; f < 1024; f += 256){
            int r = f >> 3, q = f & 7;
            float4 v = make_float4(0,0,0,0);
            if (r0 + r < nA) v = *(const float4*)&A[(size_t)(r0 + r)*EDIM + kc + q*4];
            *(float4*)&As[r*36 + q*4] = v;
        }
        for (int f = tid; f < 1024; f += 256){
            int r = f >> 3, q = f & 7;
            float4 v = make_float4(0,0,0,0);
            if (r < KTOP) v = *(const float4*)&topic[(size_t)r*EDIM + kc + q*4];
            *(float4*)&Bs[r*36 + q*4] = v;
        }
        __syncthreads();
#pragma unroll
        for (int ks = 0; ks < 4; ks++){
            int ka = ks*8 + c;
            uint32_t a0[2], a1[2], a2[2], a3[2], b0[8], b1[8];
#pragma unroll
            for (int mi = 0; mi < 2; mi++){
                int base = (wr*32 + mi*16 + g)*36 + ka;
                a0[mi] = __float_as_uint(As[base]);
                a1[mi] = __float_as_uint(As[base + 8*36]);
                a2[mi] = __float_as_uint(As[base + 4]);
                a3[mi] = __float_as_uint(As[base + 8*36 + 4]);
            }
#pragma unroll
            for (int ni = 0; ni < 8; ni++){
                int nb = (wc*64 + ni*8 + g)*36 + ka;
                b0[ni] = __float_as_uint(Bs[nb]);
                b1[ni] = __float_as_uint(Bs[nb + 4]);
            }
#pragma unroll
            for (int mi = 0; mi < 2; mi++)
#pragma unroll
                for (int ni = 0; ni < 8; ni++){
                    asm volatile(
                        "mma.sync.aligned.m16n8k8.row.col.f32.tf32.tf32.f32 "
                        "{%0,%1,%2,%3}, {%4,%5,%6,%7}, {%8,%9}, {%0,%1,%2,%3};"
                        : "+f"(acc[mi][ni][0]), "+f"(acc[mi][ni][1]),
                          "+f"(acc[mi][ni][2]), "+f"(acc[mi][ni][3])
                        : "r"(a0[mi]), "r"(a1[mi]), "r"(a2[mi]), "r"(a3[mi]),
                          "r"(b0[ni]), "r"(b1[ni]));
                }
        }
    }

#pragma unroll
    for (int mi = 0; mi < 2; mi++){
        int Rb = r0 + wr*32 + mi*16 + g;
#pragma unroll
        for (int ni = 0; ni < 8; ni++){
            int Cb = wc*64 + ni*8 + c*2;
#pragma unroll
            for (int q = 0; q < 4; q++){
                int R = Rb + ((q >= 2) ? 8 : 0);
                int C = Cb + (q & 1);
                if (R < nA && C < KTOP){
                    float M = nAarr[R] + g_nt[C] - 2.0f * acc[mi][ni][q];
                    float kv = expf(-alpha * M);
                    Mo[(size_t)R*KTOP + C] = M;
                    Ko[(size_t)R*KTOP + C] = kv;
                }
            }
        }
    }
}

// ---------------- fused persistent Sinkhorn + tb epilogue ---------------------
__device__ void sink_dt(int cta){
    __shared__ float v_sm[128], vf_sm[128], b_sm[128], spw[8][128], red[256];
    int tid = threadIdx.x, w = tid >> 5, lane = tid & 31;
    int gwid = cta*8 + w;
    const int NWRP = NC1*8;
    const float invN = 1.0f / (float)NDOC;

    if (tid < 128) b_sm[tid] = (tid < 100) ? g_b1[tid] : 0.f;
    {
        float4 p = make_float4(0,0,0,0);
        for (int i = gwid; i < NDOC; i += NWRP){
            if (lane < 25){
                float4 k = ((const float4*)(g_Kdt + (size_t)i*KTOP))[lane];
                p.x += k.x; p.y += k.y; p.z += k.z; p.w += k.w;
            }
        }
        if (lane < 25){
            spw[w][4*lane]   = p.x*invN; spw[w][4*lane+1] = p.y*invN;
            spw[w][4*lane+2] = p.z*invN; spw[w][4*lane+3] = p.w*invN;
        }
    }
    __syncthreads();
    if (tid < 100){
        float s = 0.f;
#pragma unroll
        for (int x = 0; x < 8; x++) s += spw[x][tid];
        atomicAdd(&g_s1[0][tid], s);
    }
    gbar(&g_bc1, &g_bg1, NC1);
    if (tid < 128) v_sm[tid] = (tid < 100) ? (b_sm[tid] / (g_s1[0][tid] + 1e-16f)) : 0.f;
    __syncthreads();

    float err = 1.0f; int cpt = 0;
    while (err > 0.005f && cpt < 5000){
        int it = cpt + 1;
        int buf = it % 3;
        bool chk = ((it % 50) == 1) || (it == 5000);
        if (cta == 0 && tid < 128) g_s1[(it + 1) % 3][tid] = 0.f;
        float4 vv = (lane < 25) ? ((const float4*)v_sm)[lane] : make_float4(0,0,0,0);
        float4 p = make_float4(0,0,0,0);
        for (int i = gwid; i < NDOC; i += 2*NWRP){
            int i2 = i + NWRP;
            float4 ka = make_float4(0,0,0,0), kb = make_float4(0,0,0,0);
            if (lane < 25){
                ka = ((const float4*)(g_Kdt + (size_t)i*KTOP))[lane];
                if (i2 < NDOC) kb = ((const float4*)(g_Kdt + (size_t)i2*KTOP))[lane];
            }
            float ta = ka.x*vv.x + ka.y*vv.y + ka.z*vv.z + ka.w*vv.w;
            float tb = kb.x*vv.x + kb.y*vv.y + kb.z*vv.z + kb.w*vv.w;
            ta = warp_bfly(ta); tb = warp_bfly(tb);
            float ua = invN / (ta + 1e-16f);
            if (lane == 0 && chk) g_u1[i] = ua;
            p.x += ka.x*ua; p.y += ka.y*ua; p.z += ka.z*ua; p.w += ka.w*ua;
            if (i2 < NDOC){
                float ub = invN / (tb + 1e-16f);
                if (lane == 0 && chk) g_u1[i2] = ub;
                p.x += kb.x*ub; p.y += kb.y*ub; p.z += kb.z*ub; p.w += kb.w*ub;
            }
        }
        if (lane < 25){
            spw[w][4*lane] = p.x; spw[w][4*lane+1] = p.y;
            spw[w][4*lane+2] = p.z; spw[w][4*lane+3] = p.w;
        }
        __syncthreads();
        if (tid < 100){
            float s = 0.f;
#pragma unroll
            for (int x = 0; x < 8; x++) s += spw[x][tid];
            atomicAdd(&g_s1[buf][tid], s);
        }
        cpt = it;
        gbar(&g_bc1, &g_bg1, NC1);
        float ev = 0.f;
        if (tid < 128){
            float s = (tid < 100) ? g_s1[buf][tid] : 0.f;
            float vo = v_sm[tid];
            vf_sm[tid] = vo;
            if (chk && tid < 100) ev = fabsf(vo*s - b_sm[tid]);
            v_sm[tid] = (tid < 100) ? (b_sm[tid] / (s + 1e-16f)) : 0.f;
        }
        if (chk){
            red[tid] = ev; __syncthreads();
            for (int s2 = 128; s2 > 0; s2 >>= 1){ if (tid < s2) red[tid] += red[tid+s2]; __syncthreads(); }
            err = red[0];
        }
        __syncthreads();
    }
    if (cta == 0 && tid < 100) g_v1fin[tid] = vf_sm[tid];
}

__device__ void sink_tw(int cta){
    __shared__ float u_sm[128], spw[8][128], red[256];
    int tid = threadIdx.x, w = tid >> 5, lane = tid & 31;
    int gwid = cta*8 + w;
    const int NWRP = NC2*8;
    const float invK = 1.0f / (float)KTOP;

    {
        float4 p = make_float4(0,0,0,0);
        for (int j = gwid; j < VW; j += NWRP){
            float4 k = make_float4(0,0,0,0);
            if (lane < 25) k = ((const float4*)(g_KtwT + (size_t)j*KTOP))[lane];
            float t = warp_bfly(k.x + k.y + k.z + k.w) * invK;
            float v = g_b2[j] / (t + 1e-16f);
            if (lane == 0) g_v2[j] = v;
            p.x += k.x*v; p.y += k.y*v; p.z += k.z*v; p.w += k.w*v;
        }
        if (lane < 25){
            spw[w][4*lane] = p.x; spw[w][4*lane+1] = p.y;
            spw[w][4*lane+2] = p.z; spw[w][4*lane+3] = p.w;
        }
    }
    __syncthreads();
    if (tid < 100){
        float s = 0.f;
#pragma unroll
        for (int x = 0; x < 8; x++) s += spw[x][tid];
        atomicAdd(&g_s2[0][tid], s);
    }
    gbar(&g_bc2, &g_bg2, NC2);

    float err = 1.0f; int cpt = 0;
    while (err > 0.005f && cpt < 5000){
        int it = cpt + 1;
        int buf = it % 3;
        bool chk = ((it % 50) == 1) || (it == 5000);
        bool stv = ((it % 50) == 0) || (it == 4999);
        if (cta == 0 && tid < 128) g_s2[(it + 1) % 3][tid] = 0.f;
        if (tid < 128) u_sm[tid] = (tid < 100) ? (invK / (g_s2[(it + 2) % 3][tid] + 1e-16f)) : 0.f;
        __syncthreads();
        float4 uu = (lane < 25) ? ((const float4*)u_sm)[lane] : make_float4(0,0,0,0);
        float4 p = make_float4(0,0,0,0);
        float ep = 0.f;
        for (int j = gwid; j < VW; j += 2*NWRP){
            int j2 = j + NWRP;
            float4 ka = make_float4(0,0,0,0), kb = make_float4(0,0,0,0);
            if (lane < 25){
                ka = ((const float4*)(g_KtwT + (size_t)j*KTOP))[lane];
                if (j2 < VW) kb = ((const float4*)(g_KtwT + (size_t)j2*KTOP))[lane];
            }
            float ta = ka.x*uu.x + ka.y*uu.y + ka.z*uu.z + ka.w*uu.w;
            float tb = kb.x*uu.x + kb.y*uu.y + kb.z*uu.z + kb.w*uu.w;
            ta = warp_bfly(ta); tb = warp_bfly(tb);
            float bja = g_b2[j];
            float vna = bja / (ta + 1e-16f);
            if (lane == 0){
                if (chk){ float vo = g_v2[j]; ep += fabsf(vo*ta - bja); g_v2fin[j] = vo; }
                if (stv) g_v2[j] = vna;
            }
            p.x += ka.x*vna; p.y += ka.y*vna; p.z += ka.z*vna; p.w += ka.w*vna;
            if (j2 < VW){
                float bjb = g_b2[j2];
                float vnb = bjb / (tb + 1e-16f);
                if (lane == 0){
                    if (chk){ float vo = g_v2[j2]; ep += fabsf(vo*tb - bjb); g_v2fin[j2] = vo; }
                    if (stv) g_v2[j2] = vnb;
                }
                p.x += kb.x*vnb; p.y += kb.y*vnb; p.z += kb.z*vnb; p.w += kb.w*vnb;
            }
        }
        if (lane < 25){
            spw[w][4*lane] = p.x; spw[w][4*lane+1] = p.y;
            spw[w][4*lane+2] = p.z; spw[w][4*lane+3] = p.w;
        }
        if (chk){
            red[tid] = ep; __syncthreads();
            for (int s2 = 128; s2 > 0; s2 >>= 1){ if (tid < s2) red[tid] += red[tid+s2]; __syncthreads(); }
            if (tid == 0) g_err2[cta] = red[0];
        }
        __syncthreads();
        if (tid < 100){
            float s = 0.f;
#pragma unroll
            for (int x = 0; x < 8; x++) s += spw[x][tid];
            atomicAdd(&g_s2[buf][tid], s);
        }
        cpt = it;
        gbar(&g_bc2, &g_bg2, NC2);
        if (chk){
            red[tid] = (tid < NC2) ? g_err2[tid] : 0.f; __syncthreads();
            for (int s2 = 128; s2 > 0; s2 >>= 1){ if (tid < s2) red[tid] += red[tid+s2]; __syncthreads(); }
            err = red[0];
        }
        __syncthreads();
    }
    if (cta == 0 && tid < 100) g_u2[tid] = u_sm[tid];
}

__device__ void tb_phase(int cta){
    __shared__ float red[256];
    int tid = threadIdx.x;
    const int TH = NDOC*32;
    const int TOT = TH + VWP*32;
    float pth = 0.f, pbe = 0.f;
    for (int idx = cta*256 + tid; idx < TOT; idx += 148*256){
        if (idx < TH){
            int i = idx >> 5, k4 = (idx & 31) << 2;
            float4 o = make_float4(0,0,0,0);
            if (k4 < KTOP){
                float4 kk = *(const float4*)&g_Kdt[(size_t)i*KTOP + k4];
                float4 mm = *(const float4*)&g_Mdt[(size_t)i*KTOP + k4];
                float4 vf = *(const float4*)&g_v1fin[k4];
                float u = g_u1[i];
                float t0 = u*kk.x*vf.x, t1 = u*kk.y*vf.y, t2 = u*kk.z*vf.z, t3 = u*kk.w*vf.w;
                pth += t0*mm.x + t1*mm.y + t2*mm.z + t3*mm.w;
                o = make_float4(t0*(float)NDOC, t1*(float)NDOC, t2*(float)NDOC, t3*(float)NDOC);
            }
            __nv_bfloat162 lo = __floats2bfloat162_rn(o.x, o.y);
            __nv_bfloat162 hi = __floats2bfloat162_rn(o.z, o.w);
            uint2 st; st.x = *(uint32_t*)&lo; st.y = *(uint32_t*)&hi;
            *(uint2*)&g_thetaB[(size_t)i*128 + k4] = st;
        } else {
            int jdx = idx - TH;
            int j = jdx >> 5, k4 = (jdx & 31) << 2;
            float4 o = make_float4(0,0,0,0);
            if (j < VW && k4 < KTOP){
                float4 kk = *(const float4*)&g_KtwT[(size_t)j*KTOP + k4];
                float4 mm = *(const float4*)&g_MtwT[(size_t)j*KTOP + k4];
                float4 uu = *(const float4*)&g_u2[k4];
                float v = g_v2fin[j];
                float t0 = uu.x*kk.x*v, t1 = uu.y*kk.y*v, t2 = uu.z*kk.z*v, t3 = uu.w*kk.w*v;
                pbe += t0*mm.x + t1*mm.y + t2*mm.z + t3*mm.w;
                o = make_float4(t0*(float)KTOP, t1*(float)KTOP, t2*(float)KTOP, t3*(float)KTOP);
            }
            __nv_bfloat162 lo = __floats2bfloat162_rn(o.x, o.y);
            __nv_bfloat162 hi = __floats2bfloat162_rn(o.z, o.w);
            uint2 st; st.x = *(uint32_t*)&lo; st.y = *(uint32_t*)&hi;
            *(uint2*)&g_betaB[(size_t)j*128 + k4] = st;
        }
    }
    red[tid] = pth; __syncthreads();
    for (int s = 128; s > 0; s >>= 1){ if (tid < s) red[tid] += red[tid+s]; __syncthreads(); }
    if (tid == 0) atomicAdd(&g_acc[0], (double)red[0]);
    __syncthreads();
    red[tid] = pbe; __syncthreads();
    for (int s = 128; s > 0; s >>= 1){ if (tid < s) red[tid] += red[tid+s]; __syncthreads(); }
    if (tid == 0) atomicAdd(&g_acc[1], (double)red[0]);
}

__global__ __launch_bounds__(256) void sink_fused(){
    if (blockIdx.x < NC1) sink_dt(blockIdx.x);
    else                  sink_tw(blockIdx.x - NC1);
    gbar(&g_bc3, &g_bg3, NC1 + NC2);
    tb_phase(blockIdx.x);
}

// ---------------- tensor-core recon GEMM + log-loss (ldmatrix) ----------------
// CTA tile 128x128, full K=128 in dynamic smem, 8 warps (4m x 2n) of 32x64.
// Per k16-step per warp: 2 A-ldmatrix.x4 + 4 B-ldmatrix.x4 + 16 HMMA.
#define APITCH 136
__global__ __launch_bounds__(256) void recon_kernel(const float* __restrict__ bow){
    extern __shared__ __align__(16) char dsm[];
    __nv_bfloat16* As = (__nv_bfloat16*)dsm;                     // 128 x 136
    __nv_bfloat16* Bs = (__nv_bfloat16*)(dsm + 128*APITCH*2);    // 128 x 136
    float* red = (float*)(dsm + 2*128*APITCH*2);
    int tid = threadIdx.x, lane = tid & 31, w = tid >> 5;
    int wm = w >> 1, wn = w & 1;
    int g = lane >> 2, c = lane & 3;
    int r0 = blockIdx.y * 128, c0 = blockIdx.x * 128;

    // load full tiles (coalesced uint4)
    for (int f = tid; f < 2048; f += 256){
        int r = f >> 4, q = f & 15;
        *(uint4*)&As[r*APITCH + q*8] = *(const uint4*)&g_thetaB[(size_t)(r0 + r)*128 + q*8];
    }
    for (int f = tid; f < 2048; f += 256){
        int r = f >> 4, q = f & 15;
        *(uint4*)&Bs[r*APITCH + q*8] = *(const uint4*)&g_betaB[(size_t)(c0 + r)*128 + q*8];
    }
    __syncthreads();

    float acc[2][8][4];
#pragma unroll
    for (int mi = 0; mi < 2; mi++)
#pragma unroll
        for (int ni = 0; ni < 8; ni++)
#pragma unroll
            for (int q = 0; q < 4; q++) acc[mi][ni][q] = 0.f;

    uint32_t sA = smem_u32(As), sB = smem_u32(Bs);
    int lrow = lane & 15, lhalf = (lane >> 4) << 3;   // 0 or 8 (k offset)

#pragma unroll
    for (int ks = 0; ks < 8; ks++){
        int k0 = ks * 16;
        uint32_t a[2][4], b[4][4];
#pragma unroll
        for (int mi = 0; mi < 2; mi++){
            uint32_t addr = sA + (uint32_t)(((wm*32 + mi*16 + lrow)*APITCH + k0 + lhalf) * 2);
            asm volatile("ldmatrix.sync.aligned.m8n8.x4.shared.b16 {%0,%1,%2,%3}, [%4];"
                : "=r"(a[mi][0]), "=r"(a[mi][1]), "=r"(a[mi][2]), "=r"(a[mi][3]) : "r"(addr));
        }
#pragma unroll
        for (int np = 0; np < 4; np++){
            uint32_t addr = sB + (uint32_t)(((wn*64 + np*16 + lrow)*APITCH + k0 + lhalf) * 2);
            asm volatile("ldmatrix.sync.aligned.m8n8.x4.shared.b16 {%0,%1,%2,%3}, [%4];"
                : "=r"(b[np][0]), "=r"(b[np][1]), "=r"(b[np][2]), "=r"(b[np][3]) : "r"(addr));
        }
#pragma unroll
        for (int mi = 0; mi < 2; mi++)
#pragma unroll
            for (int np = 0; np < 4; np++){
                asm volatile(
                    "mma.sync.aligned.m16n8k16.row.col.f32.bf16.bf16.f32 "
                    "{%0,%1,%2,%3}, {%4,%5,%6,%7}, {%8,%9}, {%0,%1,%2,%3};"
                    : "+f"(acc[mi][2*np][0]), "+f"(acc[mi][2*np][1]),
                      "+f"(acc[mi][2*np][2]), "+f"(acc[mi][2*np][3])
                    : "r"(a[mi][0]), "r"(a[mi][1]), "r"(a[mi][2]), "r"(a[mi][3]),
                      "r"(b[np][0]), "r"(b[np][2]));
                asm volatile(
                    "mma.sync.aligned.m16n8k16.row.col.f32.bf16.bf16.f32 "
                    "{%0,%1,%2,%3}, {%4,%5,%6,%7}, {%8,%9}, {%0,%1,%2,%3};"
                    : "+f"(acc[mi][2*np+1][0]), "+f"(acc[mi][2*np+1][1]),
                      "+f"(acc[mi][2*np+1][2]), "+f"(acc[mi][2*np+1][3])
                    : "r"(a[mi][0]), "r"(a[mi][1]), "r"(a[mi][2]), "r"(a[mi][3]),
                      "r"(b[np][1]), "r"(b[np][3]));
            }
    }

    float part = 0.f;
#pragma unroll
    for (int mi = 0; mi < 2; mi++){
        int R = r0 + wm*32 + mi*16 + g;
#pragma unroll
        for (int ni = 0; ni < 8; ni++){
            int C = c0 + wn*64 + ni*8 + c*2;
            if (C < VW){
                float2 b0 = *(const float2*)&bow[(size_t)R*VW + C];
                float2 b1 = *(const float2*)&bow[(size_t)(R + 8)*VW + C];
                part += b0.x * __logf(acc[mi][ni][0] + 1e-12f)
                      + b0.y * __logf(acc[mi][ni][1] + 1e-12f)
                      + b1.x * __logf(acc[mi][ni][2] + 1e-12f)
                      + b1.y * __logf(acc[mi][ni][3] + 1e-12f);
            }
        }
    }
    red[tid] = part; __syncthreads();
    for (int s = 128; s > 0; s >>= 1){ if (tid < s) red[tid] += red[tid+s]; __syncthreads(); }
    if (tid == 0) atomicAdd(&g_acc[2], (double)red[0]);
}
#define RECON_SMEM (2*128*APITCH*2 + 256*4)

__global__ void final_kernel(float* out){
    out[0] = (float)(g_acc[0] + g_acc[1] - g_acc[2] * (1.0 / (double)NDOC));
}

// ---------------- launch -----------------------------------------------------
extern "C" void kernel_launch(void* const* d_in, const int* in_sizes, int n_in,
                              void* d_out, int out_size)
{
    const float *bow = nullptr, *doc = nullptr, *word = nullptr,
                *topic = nullptr, *ww = nullptr, *tw = nullptr;
    for (int i = 0; i < n_in; i++){
        const float* p = (const float*)d_in[i];
        switch (in_sizes[i]){
            case 40960000: bow = p;   break;
            case 1572864:  doc = p;   break;
            case 3840000:  word = p;  break;
            case 38400:    topic = p; break;
            case 10000:    ww = p;    break;
            case 100:      tw = p;    break;
        }
    }
    float* out = (float*)d_out;

    static int smem_set = 0;
    if (!smem_set){
        cudaFuncSetAttribute(recon_kernel,
            cudaFuncAttributeMaxDynamicSharedMemorySize, RECON_SMEM);
        smem_set = 1;
    }

    prologue_kernel<<<151, 256>>>(doc, topic, word, tw, ww);
    dist_mma<<<32 + 79, 256>>>(doc, word, topic);
    sink_fused<<<NC1 + NC2, 256>>>();
    recon_kernel<<<dim3(79, 32), 256, RECON_SMEM>>>(bow);
    final_kernel<<<1, 1>>>(out);
}

// round 15
// speedup vs baseline: 1.1003x; 1.0912x over previous
#include <cuda_runtime.h>
#include <cuda_bf16.h>
#include <math.h>
#include <stdint.h>

#define NDOC 4096
#define VW   10000
#define VWP  10112           // 158*64 = 79*128
#define KTOP 100
#define EDIM 384
#define NC1  44      // DT sinkhorn CTAs
#define NC2  104     // TW sinkhorn CTAs

// ---------------- device state -----------------------------------------------
__device__ __align__(16) float g_Kdt[NDOC*KTOP];
__device__ __align__(16) float g_KtwT[VW*KTOP];
__device__ __align__(16) __nv_bfloat16 g_thetaB[NDOC*128];
__device__ __align__(16) __nv_bfloat16 g_betaB[VWP*128];
__device__ __align__(16) __nv_bfloat16 g_bowB[(size_t)NDOC*VWP];
__device__ __align__(16) float g_u1[NDOC];
__device__ __align__(16) float g_v1fin[128];
__device__ __align__(16) float g_b1[128];
__device__ __align__(16) float g_u2[128];
__device__ __align__(16) float g_v2[VW];
__device__ __align__(16) float g_v2fin[VW];
__device__ __align__(16) float g_b2[VW];
__device__ float g_nd[NDOC], g_nt[KTOP], g_nw[VW];
__device__ float g_s1[3][128];
__device__ float g_s2[3][128];
__device__ float g_err2[NC2];
__device__ double g_acc[3];
__device__ unsigned g_bc1, g_bc2, g_bc3;
__device__ volatile unsigned g_bg1, g_bg2, g_bg3;

// ---------------- helpers ----------------------------------------------------
__device__ __forceinline__ float warp_bfly(float v){
    v += __shfl_xor_sync(0xffffffffu, v, 16);
    v += __shfl_xor_sync(0xffffffffu, v, 8);
    v += __shfl_xor_sync(0xffffffffu, v, 4);
    v += __shfl_xor_sync(0xffffffffu, v, 2);
    v += __shfl_xor_sync(0xffffffffu, v, 1);
    return v;
}
__device__ __forceinline__ float warp_sum(float v){
    v += __shfl_down_sync(0xffffffffu, v, 16);
    v += __shfl_down_sync(0xffffffffu, v, 8);
    v += __shfl_down_sync(0xffffffffu, v, 4);
    v += __shfl_down_sync(0xffffffffu, v, 2);
    v += __shfl_down_sync(0xffffffffu, v, 1);
    return v;
}
__device__ __forceinline__ void gbar(unsigned* cnt, volatile unsigned* gen, unsigned nb){
    __syncthreads();
    if (threadIdx.x == 0){
        __threadfence();
        unsigned g = *gen;
        if (atomicAdd(cnt, 1u) == nb - 1u){
            *cnt = 0u; __threadfence(); *gen = g + 1u;
        } else {
            while (*gen == g) { __nanosleep(32); }
            __threadfence();
        }
    }
    __syncthreads();
}
__device__ __forceinline__ uint32_t smem_u32(const void* p){
    uint32_t a;
    asm("{ .reg .u64 t; cvta.to.shared.u64 t, %1; cvt.u32.u64 %0, t; }" : "=r"(a) : "l"(p));
    return a;
}

// ---------------- fused prologue: init + norms + softmax ----------------------
__global__ __launch_bounds__(256) void prologue_kernel(
    const float* __restrict__ doc, const float* __restrict__ topic,
    const float* __restrict__ word, const float* __restrict__ tw,
    const float* __restrict__ ww)
{
    __shared__ float red[256];
    int b = blockIdx.x, tid = threadIdx.x;
    if (b < 148){
        int lane = tid & 31, w = tid >> 5;
        int gw = b*8 + w;
        const int TOT = NDOC + KTOP + VW;
        for (int row = gw; row < TOT; row += 148*8){
            const float4* src; float* dst;
            if (row < NDOC){ src = (const float4*)(doc + (size_t)row*EDIM); dst = &g_nd[row]; }
            else if (row < NDOC + KTOP){ src = (const float4*)(topic + (size_t)(row-NDOC)*EDIM); dst = &g_nt[row-NDOC]; }
            else { src = (const float4*)(word + (size_t)(row-NDOC-KTOP)*EDIM); dst = &g_nw[row-NDOC-KTOP]; }
            float4 a = src[lane], c = src[lane+32], d = src[lane+64];
            float s = a.x*a.x + a.y*a.y + a.z*a.z + a.w*a.w
                    + c.x*c.x + c.y*c.y + c.z*c.z + c.w*c.w
                    + d.x*d.x + d.y*d.y + d.z*d.z + d.w*d.w;
            s = warp_sum(s);
            if (lane == 0) *dst = s;
        }
    } else if (b == 148 || b == 149){
        const float* x = (b == 148) ? tw : ww;
        float* out = (b == 148) ? g_b1 : g_b2;
        int n = (b == 148) ? KTOP : VW;
        float m = -3.4e38f;
        for (int i = tid; i < n; i += 256) m = fmaxf(m, x[i]);
        red[tid] = m; __syncthreads();
        for (int s = 128; s > 0; s >>= 1){ if (tid < s) red[tid] = fmaxf(red[tid], red[tid+s]); __syncthreads(); }
        m = red[0]; __syncthreads();
        float sum = 0.f;
        for (int i = tid; i < n; i += 256) sum += expf(x[i] - m);
        red[tid] = sum; __syncthreads();
        for (int s = 128; s > 0; s >>= 1){ if (tid < s) red[tid] += red[tid+s]; __syncthreads(); }
        sum = red[0]; __syncthreads();
        float inv = 1.0f / sum;
        for (int i = tid; i < n; i += 256) out[i] = expf(x[i] - m) * inv;
    } else {
        if (tid == 0){
            g_bc1 = 0u; g_bc2 = 0u; g_bc3 = 0u;
            g_bg1 = 0u; g_bg2 = 0u; g_bg3 = 0u;
            g_acc[0] = 0.0; g_acc[1] = 0.0; g_acc[2] = 0.0;
        }
        if (tid < 128){
#pragma unroll
            for (int q = 0; q < 3; q++){ g_s1[q][tid] = 0.f; g_s2[q][tid] = 0.f; }
        }
    }
}

// ---------------- tf32 tensor-core distance kernel (K only) -------------------
__global__ __launch_bounds__(256) void dist_mma(
    const float* __restrict__ doc, const float* __restrict__ word,
    const float* __restrict__ topic)
{
    __shared__ float As[128*36];
    __shared__ float Bs[128*36];
    int tid = threadIdx.x, lane = tid & 31, w = tid >> 5;
    int wr = w >> 1, wc = w & 1;
    int g = lane >> 2, c = lane & 3;
    int by = blockIdx.x;
    bool dt = (by < 32);
    const float* A = dt ? doc : word;
    int nA = dt ? NDOC : VW;
    int r0 = (dt ? by : (by - 32)) * 128;
    float alpha = dt ? 3.0f : 2.0f;
    const float* nAarr = dt ? g_nd : g_nw;
    float* Ko = dt ? g_Kdt : g_KtwT;

    float acc[2][8][4];
#pragma unroll
    for (int mi = 0; mi < 2; mi++)
#pragma unroll
        for (int ni = 0; ni < 8; ni++)
#pragma unroll
            for (int q = 0; q < 4; q++) acc[mi][ni][q] = 0.f;

    for (int chunk = 0; chunk < 12; chunk++){
        int kc = chunk * 32;
        __syncthreads();
        for (int f = tid; f < 1024; f += 256){
            int r = f >> 3, q = f & 7;
            float4 v = make_float4(0,0,0,0);
            if (r0 + r < nA) v = *(const float4*)&A[(size_t)(r0 + r)*EDIM + kc + q*4];
            *(float4*)&As[r*36 + q*4] = v;
        }
        for (int f = tid; f < 1024; f += 256){
            int r = f >> 3, q = f & 7;
            float4 v = make_float4(0,0,0,0);
            if (r < KTOP) v = *(const float4*)&topic[(size_t)r*EDIM + kc + q*4];
            *(float4*)&Bs[r*36 + q*4] = v;
        }
        __syncthreads();
#pragma unroll
        for (int ks = 0; ks < 4; ks++){
            int ka = ks*8 + c;
            uint32_t a0[2], a1[2], a2[2], a3[2], b0[8], b1[8];
#pragma unroll
            for (int mi = 0; mi < 2; mi++){
                int base = (wr*32 + mi*16 + g)*36 + ka;
                a0[mi] = __float_as_uint(As[base]);
                a1[mi] = __float_as_uint(As[base + 8*36]);
                a2[mi] = __float_as_uint(As[base + 4]);
                a3[mi] = __float_as_uint(As[base + 8*36 + 4]);
            }
#pragma unroll
            for (int ni = 0; ni < 8; ni++){
                int nb = (wc*64 + ni*8 + g)*36 + ka;
                b0[ni] = __float_as_uint(Bs[nb]);
                b1[ni] = __float_as_uint(Bs[nb + 4]);
            }
#pragma unroll
            for (int mi = 0; mi < 2; mi++)
#pragma unroll
                for (int ni = 0; ni < 8; ni++){
                    asm volatile(
                        "mma.sync.aligned.m16n8k8.row.col.f32.tf32.tf32.f32 "
                        "{%0,%1,%2,%3}, {%4,%5,%6,%7}, {%8,%9}, {%0,%1,%2,%3};"
                        : "+f"(acc[mi][ni][0]), "+f"(acc[mi][ni][1]),
                          "+f"(acc[mi][ni][2]), "+f"(acc[mi][ni][3])
                        : "r"(a0[mi]), "r"(a1[mi]), "r"(a2[mi]), "r"(a3[mi]),
                          "r"(b0[ni]), "r"(b1[ni]));
                }
        }
    }

#pragma unroll
    for (int mi = 0; mi < 2; mi++){
        int Rb = r0 + wr*32 + mi*16 + g;
#pragma unroll
        for (int ni = 0; ni < 8; ni++){
            int Cb = wc*64 + ni*8 + c*2;
#pragma unroll
            for (int q = 0; q < 4; q++){
                int R = Rb + ((q >= 2) ? 8 : 0);
                int C = Cb + (q & 1);
                if (R < nA && C < KTOP){
                    float M = nAarr[R] + g_nt[C] - 2.0f * acc[mi][ni][q];
                    Ko[(size_t)R*KTOP + C] = expf(-alpha * M);
                }
            }
        }
    }
}

// ---------------- fused persistent Sinkhorn + bow convert + tb ----------------
__device__ void sink_dt(int cta){
    __shared__ float v_sm[128], vf_sm[128], b_sm[128], spw[8][128], red[256];
    int tid = threadIdx.x, w = tid >> 5, lane = tid & 31;
    int gwid = cta*8 + w;
    const int NWRP = NC1*8;
    const float invN = 1.0f / (float)NDOC;

    if (tid < 128) b_sm[tid] = (tid < 100) ? g_b1[tid] : 0.f;
    {
        float4 p = make_float4(0,0,0,0);
        for (int i = gwid; i < NDOC; i += NWRP){
            if (lane < 25){
                float4 k = ((const float4*)(g_Kdt + (size_t)i*KTOP))[lane];
                p.x += k.x; p.y += k.y; p.z += k.z; p.w += k.w;
            }
        }
        if (lane < 25){
            spw[w][4*lane]   = p.x*invN; spw[w][4*lane+1] = p.y*invN;
            spw[w][4*lane+2] = p.z*invN; spw[w][4*lane+3] = p.w*invN;
        }
    }
    __syncthreads();
    if (tid < 100){
        float s = 0.f;
#pragma unroll
        for (int x = 0; x < 8; x++) s += spw[x][tid];
        atomicAdd(&g_s1[0][tid], s);
    }
    gbar(&g_bc1, &g_bg1, NC1);
    if (tid < 128) v_sm[tid] = (tid < 100) ? (b_sm[tid] / (g_s1[0][tid] + 1e-16f)) : 0.f;
    __syncthreads();

    float err = 1.0f; int cpt = 0;
    while (err > 0.005f && cpt < 5000){
        int it = cpt + 1;
        int buf = it % 3;
        bool chk = ((it % 50) == 1) || (it == 5000);
        if (cta == 0 && tid < 128) g_s1[(it + 1) % 3][tid] = 0.f;
        float4 vv = (lane < 25) ? ((const float4*)v_sm)[lane] : make_float4(0,0,0,0);
        float4 p = make_float4(0,0,0,0);
        for (int i = gwid; i < NDOC; i += 2*NWRP){
            int i2 = i + NWRP;
            float4 ka = make_float4(0,0,0,0), kb = make_float4(0,0,0,0);
            if (lane < 25){
                ka = ((const float4*)(g_Kdt + (size_t)i*KTOP))[lane];
                if (i2 < NDOC) kb = ((const float4*)(g_Kdt + (size_t)i2*KTOP))[lane];
            }
            float ta = ka.x*vv.x + ka.y*vv.y + ka.z*vv.z + ka.w*vv.w;
            float tb = kb.x*vv.x + kb.y*vv.y + kb.z*vv.z + kb.w*vv.w;
            ta = warp_bfly(ta); tb = warp_bfly(tb);
            float ua = invN / (ta + 1e-16f);
            if (lane == 0 && chk) g_u1[i] = ua;
            p.x += ka.x*ua; p.y += ka.y*ua; p.z += ka.z*ua; p.w += ka.w*ua;
            if (i2 < NDOC){
                float ub = invN / (tb + 1e-16f);
                if (lane == 0 && chk) g_u1[i2] = ub;
                p.x += kb.x*ub; p.y += kb.y*ub; p.z += kb.z*ub; p.w += kb.w*ub;
            }
        }
        if (lane < 25){
            spw[w][4*lane] = p.x; spw[w][4*lane+1] = p.y;
            spw[w][4*lane+2] = p.z; spw[w][4*lane+3] = p.w;
        }
        __syncthreads();
        if (tid < 100){
            float s = 0.f;
#pragma unroll
            for (int x = 0; x < 8; x++) s += spw[x][tid];
            atomicAdd(&g_s1[buf][tid], s);
        }
        cpt = it;
        gbar(&g_bc1, &g_bg1, NC1);
        float ev = 0.f;
        if (tid < 128){
            float s = (tid < 100) ? g_s1[buf][tid] : 0.f;
            float vo = v_sm[tid];
            vf_sm[tid] = vo;
            if (chk && tid < 100) ev = fabsf(vo*s - b_sm[tid]);
            v_sm[tid] = (tid < 100) ? (b_sm[tid] / (s + 1e-16f)) : 0.f;
        }
        if (chk){
            red[tid] = ev; __syncthreads();
            for (int s2 = 128; s2 > 0; s2 >>= 1){ if (tid < s2) red[tid] += red[tid+s2]; __syncthreads(); }
            err = red[0];
        }
        __syncthreads();
    }
    if (cta == 0 && tid < 100) g_v1fin[tid] = vf_sm[tid];
}

__device__ void sink_tw(int cta){
    __shared__ float u_sm[128], spw[8][128], red[256];
    int tid = threadIdx.x, w = tid >> 5, lane = tid & 31;
    int gwid = cta*8 + w;
    const int NWRP = NC2*8;
    const float invK = 1.0f / (float)KTOP;

    {
        float4 p = make_float4(0,0,0,0);
        for (int j = gwid; j < VW; j += NWRP){
            float4 k = make_float4(0,0,0,0);
            if (lane < 25) k = ((const float4*)(g_KtwT + (size_t)j*KTOP))[lane];
            float t = warp_bfly(k.x + k.y + k.z + k.w) * invK;
            float v = g_b2[j] / (t + 1e-16f);
            if (lane == 0) g_v2[j] = v;
            p.x += k.x*v; p.y += k.y*v; p.z += k.z*v; p.w += k.w*v;
        }
        if (lane < 25){
            spw[w][4*lane] = p.x; spw[w][4*lane+1] = p.y;
            spw[w][4*lane+2] = p.z; spw[w][4*lane+3] = p.w;
        }
    }
    __syncthreads();
    if (tid < 100){
        float s = 0.f;
#pragma unroll
        for (int x = 0; x < 8; x++) s += spw[x][tid];
        atomicAdd(&g_s2[0][tid], s);
    }
    gbar(&g_bc2, &g_bg2, NC2);

    float err = 1.0f; int cpt = 0;
    while (err > 0.005f && cpt < 5000){
        int it = cpt + 1;
        int buf = it % 3;
        bool chk = ((it % 50) == 1) || (it == 5000);
        bool stv = ((it % 50) == 0) || (it == 4999);
        if (cta == 0 && tid < 128) g_s2[(it + 1) % 3][tid] = 0.f;
        if (tid < 128) u_sm[tid] = (tid < 100) ? (invK / (g_s2[(it + 2) % 3][tid] + 1e-16f)) : 0.f;
        __syncthreads();
        float4 uu = (lane < 25) ? ((const float4*)u_sm)[lane] : make_float4(0,0,0,0);
        float4 p = make_float4(0,0,0,0);
        float ep = 0.f;
        for (int j = gwid; j < VW; j += 2*NWRP){
            int j2 = j + NWRP;
            float4 ka = make_float4(0,0,0,0), kb = make_float4(0,0,0,0);
            if (lane < 25){
                ka = ((const float4*)(g_KtwT + (size_t)j*KTOP))[lane];
                if (j2 < VW) kb = ((const float4*)(g_KtwT + (size_t)j2*KTOP))[lane];
            }
            float ta = ka.x*uu.x + ka.y*uu.y + ka.z*uu.z + ka.w*uu.w;
            float tb = kb.x*uu.x + kb.y*uu.y + kb.z*uu.z + kb.w*uu.w;
            ta = warp_bfly(ta); tb = warp_bfly(tb);
            float bja = g_b2[j];
            float vna = bja / (ta + 1e-16f);
            if (lane == 0){
                if (chk){ float vo = g_v2[j]; ep += fabsf(vo*ta - bja); g_v2fin[j] = vo; }
                if (stv) g_v2[j] = vna;
            }
            p.x += ka.x*vna; p.y += ka.y*vna; p.z += ka.z*vna; p.w += ka.w*vna;
            if (j2 < VW){
                float bjb = g_b2[j2];
                float vnb = bjb / (tb + 1e-16f);
                if (lane == 0){
                    if (chk){ float vo = g_v2[j2]; ep += fabsf(vo*tb - bjb); g_v2fin[j2] = vo; }
                    if (stv) g_v2[j2] = vnb;
                }
                p.x += kb.x*vnb; p.y += kb.y*vnb; p.z += kb.z*vnb; p.w += kb.w*vnb;
            }
        }
        if (lane < 25){
            spw[w][4*lane] = p.x; spw[w][4*lane+1] = p.y;
            spw[w][4*lane+2] = p.z; spw[w][4*lane+3] = p.w;
        }
        if (chk){
            red[tid] = ep; __syncthreads();
            for (int s2 = 128; s2 > 0; s2 >>= 1){ if (tid < s2) red[tid] += red[tid+s2]; __syncthreads(); }
            if (tid == 0) g_err2[cta] = red[0];
        }
        __syncthreads();
        if (tid < 100){
            float s = 0.f;
#pragma unroll
            for (int x = 0; x < 8; x++) s += spw[x][tid];
            atomicAdd(&g_s2[buf][tid], s);
        }
        cpt = it;
        gbar(&g_bc2, &g_bg2, NC2);
        if (chk){
            red[tid] = (tid < NC2) ? g_err2[tid] : 0.f; __syncthreads();
            for (int s2 = 128; s2 > 0; s2 >>= 1){ if (tid < s2) red[tid] += red[tid+s2]; __syncthreads(); }
            err = red[0];
        }
        __syncthreads();
    }
    if (cta == 0 && tid < 100) g_u2[tid] = u_sm[tid];
}

// bow fp32 -> bf16 (padded cols zeroed); runs on converter CTAs overlapping sinkhorn
__device__ void bow_convert(int cta, const float* __restrict__ bow){
    int tid = threadIdx.x;
    const int CPR = VWP/8;          // 1264 chunks of 8 per row
    const int TOT = NDOC*CPR;
    for (int idx = cta*256 + tid; idx < TOT; idx += 148*256){
        int row = idx / CPR, cc = (idx - row*CPR)*8;
        uint4 st;
        if (cc < VW){
            float4 f0 = *(const float4*)&bow[(size_t)row*VW + cc];
            float4 f1 = *(const float4*)&bow[(size_t)row*VW + cc + 4];
            __nv_bfloat162 h0 = __floats2bfloat162_rn(f0.x, f0.y);
            __nv_bfloat162 h1 = __floats2bfloat162_rn(f0.z, f0.w);
            __nv_bfloat162 h2 = __floats2bfloat162_rn(f1.x, f1.y);
            __nv_bfloat162 h3 = __floats2bfloat162_rn(f1.z, f1.w);
            st.x = *(uint32_t*)&h0; st.y = *(uint32_t*)&h1;
            st.z = *(uint32_t*)&h2; st.w = *(uint32_t*)&h3;
        } else {
            st = make_uint4(0,0,0,0);
        }
        *(uint4*)&g_bowB[(size_t)row*VWP + cc] = st;
    }
}

__device__ void tb_phase(int cta){
    __shared__ float red[256];
    int tid = threadIdx.x;
    const int TH = NDOC*32;
    const int TOT = TH + VWP*32;
    const float i3 = 1.0f/3.0f, i2 = 0.5f;
    float pth = 0.f, pbe = 0.f;
    for (int idx = cta*256 + tid; idx < TOT; idx += 148*256){
        if (idx < TH){
            int i = idx >> 5, k4 = (idx & 31) << 2;
            float4 o = make_float4(0,0,0,0);
            if (k4 < KTOP){
                float4 kk = *(const float4*)&g_Kdt[(size_t)i*KTOP + k4];
                float4 vf = *(const float4*)&g_v1fin[k4];
                float u = g_u1[i];
                float t0 = u*kk.x*vf.x, t1 = u*kk.y*vf.y, t2 = u*kk.z*vf.z, t3 = u*kk.w*vf.w;
                // M = -log(K)/3
                pth -= (t0*__logf(kk.x) + t1*__logf(kk.y) + t2*__logf(kk.z) + t3*__logf(kk.w)) * i3;
                o = make_float4(t0*(float)NDOC, t1*(float)NDOC, t2*(float)NDOC, t3*(float)NDOC);
            }
            __nv_bfloat162 lo = __floats2bfloat162_rn(o.x, o.y);
            __nv_bfloat162 hi = __floats2bfloat162_rn(o.z, o.w);
            uint2 st; st.x = *(uint32_t*)&lo; st.y = *(uint32_t*)&hi;
            *(uint2*)&g_thetaB[(size_t)i*128 + k4] = st;
        } else {
            int jdx = idx - TH;
            int j = jdx >> 5, k4 = (jdx & 31) << 2;
            float4 o = make_float4(0,0,0,0);
            if (j < VW && k4 < KTOP){
                float4 kk = *(const float4*)&g_KtwT[(size_t)j*KTOP + k4];
                float4 uu = *(const float4*)&g_u2[k4];
                float v = g_v2fin[j];
                float t0 = uu.x*kk.x*v, t1 = uu.y*kk.y*v, t2 = uu.z*kk.z*v, t3 = uu.w*kk.w*v;
                // M = -log(K)/2
                pbe -= (t0*__logf(kk.x) + t1*__logf(kk.y) + t2*__logf(kk.z) + t3*__logf(kk.w)) * i2;
                o = make_float4(t0*(float)KTOP, t1*(float)KTOP, t2*(float)KTOP, t3*(float)KTOP);
            }
            __nv_bfloat162 lo = __floats2bfloat162_rn(o.x, o.y);
            __nv_bfloat162 hi = __floats2bfloat162_rn(o.z, o.w);
            uint2 st; st.x = *(uint32_t*)&lo; st.y = *(uint32_t*)&hi;
            *(uint2*)&g_betaB[(size_t)j*128 + k4] = st;
        }
    }
    red[tid] = pth; __syncthreads();
    for (int s = 128; s > 0; s >>= 1){ if (tid < s) red[tid] += red[tid+s]; __syncthreads(); }
    if (tid == 0) atomicAdd(&g_acc[0], (double)red[0]);
    __syncthreads();
    red[tid] = pbe; __syncthreads();
    for (int s = 128; s > 0; s >>= 1){ if (tid < s) red[tid] += red[tid+s]; __syncthreads(); }
    if (tid == 0) atomicAdd(&g_acc[1], (double)red[0]);
}

__global__ __launch_bounds__(256) void sink_fused(const float* __restrict__ bow){
    int b = blockIdx.x;
    if (b >= 148){ bow_convert(b - 148, bow); return; }
    if (b < NC1) sink_dt(b);
    else         sink_tw(b - NC1);
    gbar(&g_bc3, &g_bg3, 148);
    tb_phase(b);
}

// ---------------- tensor-core recon GEMM + log-loss ---------------------------
// CTA 128x64, K=128 resident; bow tile (bf16) cp.async-prefetched to smem.
// 8 warps (4m x 2n), warp tile 32x32. Epilogue is pure smem.
#define APITCH 136
#define BOWP   72
#define RECON_SMEM (128*APITCH*2 + 64*APITCH*2 + 128*BOWP*2 + 256*4)
__global__ __launch_bounds__(256) void recon_kernel(){
    extern __shared__ __align__(16) char dsm[];
    __nv_bfloat16* As = (__nv_bfloat16*)dsm;                          // 128 x 136
    __nv_bfloat16* Bs = (__nv_bfloat16*)(dsm + 128*APITCH*2);         // 64 x 136
    __nv_bfloat16* Ws = (__nv_bfloat16*)(dsm + 128*APITCH*2 + 64*APITCH*2); // 128 x 72
    float* red = (float*)(dsm + 128*APITCH*2 + 64*APITCH*2 + 128*BOWP*2);
    int tid = threadIdx.x, lane = tid & 31, w = tid >> 5;
    int wm = w >> 1, wn = w & 1;
    int g = lane >> 2, c = lane & 3;
    int r0 = blockIdx.y * 128, c0 = blockIdx.x * 64;

    // 1) bow tile via cp.async (DRAM latency hidden behind theta/beta staging)
    uint32_t wsb = smem_u32(Ws);
    for (int f = tid; f < 1024; f += 256){
        int r = f >> 3, q = f & 7;
        uint32_t dst = wsb + (uint32_t)((r*BOWP + q*8) * 2);
        const __nv_bfloat16* src = &g_bowB[(size_t)(r0 + r)*VWP + c0 + q*8];
        asm volatile("cp.async.ca.shared.global [%0], [%1], 16;" :: "r"(dst), "l"(src));
    }
    asm volatile("cp.async.commit_group;");

    // 2) theta / beta tiles (L2-resident)
    for (int f = tid; f < 2048; f += 256){
        int r = f >> 4, q = f & 15;
        *(uint4*)&As[r*APITCH + q*8] = *(const uint4*)&g_thetaB[(size_t)(r0 + r)*128 + q*8];
    }
    for (int f = tid; f < 1024; f += 256){
        int r = f >> 4, q = f & 15;
        *(uint4*)&Bs[r*APITCH + q*8] = *(const uint4*)&g_betaB[(size_t)(c0 + r)*128 + q*8];
    }
    asm volatile("cp.async.wait_group 0;");
    __syncthreads();

    float acc[2][4][4];
#pragma unroll
    for (int mi = 0; mi < 2; mi++)
#pragma unroll
        for (int ni = 0; ni < 4; ni++)
#pragma unroll
            for (int q = 0; q < 4; q++) acc[mi][ni][q] = 0.f;

    uint32_t sA = smem_u32(As), sB = smem_u32(Bs);
    int lrow = lane & 15, lhalf = (lane >> 4) << 3;

#pragma unroll
    for (int ks = 0; ks < 8; ks++){
        int k0 = ks * 16;
        uint32_t a[2][4], b[2][4];
#pragma unroll
        for (int mi = 0; mi < 2; mi++){
            uint32_t addr = sA + (uint32_t)(((wm*32 + mi*16 + lrow)*APITCH + k0 + lhalf) * 2);
            asm volatile("ldmatrix.sync.aligned.m8n8.x4.shared.b16 {%0,%1,%2,%3}, [%4];"
                : "=r"(a[mi][0]), "=r"(a[mi][1]), "=r"(a[mi][2]), "=r"(a[mi][3]) : "r"(addr));
        }
#pragma unroll
        for (int np = 0; np < 2; np++){
            uint32_t addr = sB + (uint32_t)(((wn*32 + np*16 + lrow)*APITCH + k0 + lhalf) * 2);
            asm volatile("ldmatrix.sync.aligned.m8n8.x4.shared.b16 {%0,%1,%2,%3}, [%4];"
                : "=r"(b[np][0]), "=r"(b[np][1]), "=r"(b[np][2]), "=r"(b[np][3]) : "r"(addr));
        }
#pragma unroll
        for (int mi = 0; mi < 2; mi++)
#pragma unroll
            for (int np = 0; np < 2; np++){
                asm volatile(
                    "mma.sync.aligned.m16n8k16.row.col.f32.bf16.bf16.f32 "
                    "{%0,%1,%2,%3}, {%4,%5,%6,%7}, {%8,%9}, {%0,%1,%2,%3};"
                    : "+f"(acc[mi][2*np][0]), "+f"(acc[mi][2*np][1]),
                      "+f"(acc[mi][2*np][2]), "+f"(acc[mi][2*np][3])
                    : "r"(a[mi][0]), "r"(a[mi][1]), "r"(a[mi][2]), "r"(a[mi][3]),
                      "r"(b[np][0]), "r"(b[np][2]));
                asm volatile(
                    "mma.sync.aligned.m16n8k16.row.col.f32.bf16.bf16.f32 "
                    "{%0,%1,%2,%3}, {%4,%5,%6,%7}, {%8,%9}, {%0,%1,%2,%3};"
                    : "+f"(acc[mi][2*np+1][0]), "+f"(acc[mi][2*np+1][1]),
                      "+f"(acc[mi][2*np+1][2]), "+f"(acc[mi][2*np+1][3])
                    : "r"(a[mi][0]), "r"(a[mi][1]), "r"(a[mi][2]), "r"(a[mi][3]),
                      "r"(b[np][1]), "r"(b[np][3]));
            }
    }

    // epilogue: bow from smem (conflict-free: bank = 4*row + c)
    float part = 0.f;
#pragma unroll
    for (int mi = 0; mi < 2; mi++){
        int Rl = wm*32 + mi*16 + g;
#pragma unroll
        for (int ni = 0; ni < 4; ni++){
            int Cl = wn*32 + ni*8 + c*2;
            uint32_t w0 = *(const uint32_t*)&Ws[Rl*BOWP + Cl];
            uint32_t w1 = *(const uint32_t*)&Ws[(Rl + 8)*BOWP + Cl];
            __nv_bfloat162 h0 = *(__nv_bfloat162*)&w0;
            __nv_bfloat162 h1 = *(__nv_bfloat162*)&w1;
            part += __bfloat162float(h0.x) * __logf(acc[mi][ni][0] + 1e-12f)
                  + __bfloat162float(h0.y) * __logf(acc[mi][ni][1] + 1e-12f)
                  + __bfloat162float(h1.x) * __logf(acc[mi][ni][2] + 1e-12f)
                  + __bfloat162float(h1.y) * __logf(acc[mi][ni][3] + 1e-12f);
        }
    }
    red[tid] = part; __syncthreads();
    for (int s = 128; s > 0; s >>= 1){ if (tid < s) red[tid] += red[tid+s]; __syncthreads(); }
    if (tid == 0) atomicAdd(&g_acc[2], (double)red[0]);
}

__global__ void final_kernel(float* out){
    out[0] = (float)(g_acc[0] + g_acc[1] - g_acc[2] * (1.0 / (double)NDOC));
}

// ---------------- launch -----------------------------------------------------
extern "C" void kernel_launch(void* const* d_in, const int* in_sizes, int n_in,
                              void* d_out, int out_size)
{
    const float *bow = nullptr, *doc = nullptr, *word = nullptr,
                *topic = nullptr, *ww = nullptr, *tw = nullptr;
    for (int i = 0; i < n_in; i++){
        const float* p = (const float*)d_in[i];
        switch (in_sizes[i]){
            case 40960000: bow = p;   break;
            case 1572864:  doc = p;   break;
            case 3840000:  word = p;  break;
            case 38400:    topic = p; break;
            case 10000:    ww = p;    break;
            case 100:      tw = p;    break;
        }
    }
    float* out = (float*)d_out;

    static int smem_set = 0;
    if (!smem_set){
        cudaFuncSetAttribute(recon_kernel,
            cudaFuncAttributeMaxDynamicSharedMemorySize, RECON_SMEM);
        smem_set = 1;
    }

    prologue_kernel<<<151, 256>>>(doc, topic, word, tw, ww);
    dist_mma<<<32 + 79, 256>>>(doc, word, topic);
    sink_fused<<<296, 256>>>(bow);
    recon_kernel<<<dim3(158, 32), 256, RECON_SMEM>>>();
    final_kernel<<<1, 1>>>(out);
}